// round 3
// baseline (speedup 1.0000x reference)
#include <cuda_runtime.h>
#include <stdint.h>
#include <math.h>

#define HH 96
#define WW 96
#define NPIX 9216
#define NB 32
#define NS 50
#define KNN 5

// ---------------- scratch (no allocations allowed) ----------------
__device__ float g_cmax[NB * 3];
__device__ int   g_sel_idx[NB * 2 * NS];   // [img][cls(0=fg,1=bg)][50]
__device__ float g_train[NB * 100 * 5];    // standardized train feats
__device__ float g_meanstd[NB * 10];       // mean[5], std[5]

// ---------------- threefry2x32 core (jax/_src/prng.py) ----------------
__device__ __forceinline__ void tf2x32(uint32_t k0, uint32_t k1,
                                       uint32_t c0, uint32_t c1,
                                       uint32_t& o0, uint32_t& o1) {
    uint32_t ks2 = k0 ^ k1 ^ 0x1BD11BDAu;
    uint32_t x0 = c0 + k0, x1 = c1 + k1;
#define TF_RND(r) { x0 += x1; x1 = (x1 << (r)) | (x1 >> (32 - (r))); x1 ^= x0; }
    TF_RND(13) TF_RND(15) TF_RND(26) TF_RND(6)   x0 += k1;  x1 += ks2 + 1u;
    TF_RND(17) TF_RND(29) TF_RND(16) TF_RND(24)  x0 += ks2; x1 += k0 + 2u;
    TF_RND(13) TF_RND(15) TF_RND(26) TF_RND(6)   x0 += k0;  x1 += k1 + 3u;
    TF_RND(17) TF_RND(29) TF_RND(16) TF_RND(24)  x0 += k1;  x1 += ks2 + 4u;
    TF_RND(13) TF_RND(15) TF_RND(26) TF_RND(6)   x0 += ks2; x1 += k0 + 5u;
#undef TF_RND
    o0 = x0; o1 = x1;
}

// ---- PARTITIONABLE threefry (jax_threefry_partitionable=True, default) ----
// split(key, n)[i] = threefry2x32(key, (hi64(i)=0, lo64(i)=i)) -> (o0, o1)
// random_bits(key, 32, (N,))[p] = o0 ^ o1 of threefry2x32(key, (0, p))

// keys for image b: key_b = split(key(42)=(0,42), 32)[b]; (k_fg,k_bg)=split(key_b,2)
__device__ __forceinline__ void image_keys(int b, uint32_t& f0, uint32_t& f1,
                                           uint32_t& g0, uint32_t& g1) {
    uint32_t kb0, kb1;
    tf2x32(0u, 42u, 0u, (uint32_t)b, kb0, kb1);      // key_b
    tf2x32(kb0, kb1, 0u, 0u, f0, f1);                // k_fg = split(key_b)[0]
    tf2x32(kb0, kb1, 0u, 1u, g0, g1);                // k_bg = split(key_b)[1]
}

// uniform(key,(9216,))[p] under partitionable random_bits
__device__ __forceinline__ float u01(uint32_t k0, uint32_t k1, int p) {
    uint32_t o0, o1;
    tf2x32(k0, k1, 0u, (uint32_t)p, o0, o1);
    uint32_t bits = o0 ^ o1;
    uint32_t fb = (bits >> 9) | 0x3F800000u;
    return __uint_as_float(fb) - 1.0f;   // in [0,1); max(0,.) identity
}

// img_p = clip(img/255, 0, 1) — IEEE division to match XLA
__device__ __forceinline__ float clip255(float x) {
    return fminf(fmaxf(x / 255.0f, 0.0f), 1.0f);
}

// ---------------- kernel 1: per-channel max of img_p ----------------
__global__ void k_cmax(const float* __restrict__ img) {
    __shared__ float red[256];
    int b = blockIdx.x, t = threadIdx.x;
    const float* base = img + (size_t)b * NPIX * 3;
    for (int c = 0; c < 3; c++) {
        float m = -3.4e38f;
        for (int p = t; p < NPIX; p += 256) m = fmaxf(m, clip255(base[p * 3 + c]));
        red[t] = m; __syncthreads();
        for (int s = 128; s > 0; s >>= 1) {
            if (t < s) red[t] = fmaxf(red[t], red[t + s]);
            __syncthreads();
        }
        if (t == 0) g_cmax[b * 3 + c] = red[0];
        __syncthreads();
    }
}

// ---------------- kernel 2: top-50 index selection (fg & bg) ----------------
// blockIdx.x = image*2 + cls. top_k semantics: descending value, lowest index on tie.
__global__ void __launch_bounds__(1024) k_select(const float* __restrict__ img) {
    __shared__ uint32_t sc[NPIX];                 // monotone-mapped scores
    __shared__ unsigned long long warpbest[32];
    __shared__ uint32_t skey[2];
    __shared__ float cm[3];

    int blk = blockIdx.x, b = blk >> 1, cls = blk & 1;
    int t = threadIdx.x;
    if (t == 0) {
        uint32_t f0, f1, g0, g1;
        image_keys(b, f0, f1, g0, g1);
        skey[0] = cls ? g0 : f0;
        skey[1] = cls ? g1 : f1;
    }
    if (t < 3) cm[t] = g_cmax[b * 3 + t];
    __syncthreads();

    uint32_t k0 = skey[0], k1 = skey[1];
    const float* base = img + (size_t)b * NPIX * 3;
    for (int p = t; p < NPIX; p += 1024) {
        bool fg = false;
        #pragma unroll
        for (int c = 0; c < 3; c++) {
            float v = clip255(base[p * 3 + c]) / cm[c];   // img_norm
            if (v > 0.0f && v < 0.6f) fg = true;          // cleaned > 0
        }
        bool valid = cls ? !fg : fg;
        float s = valid ? u01(k0, k1, p) : -1.0f;
        uint32_t bits = __float_as_uint(s);
        uint32_t mapped = (bits & 0x80000000u) ? ~bits : (bits | 0x80000000u);
        sc[p] = mapped;
    }
    __syncthreads();

    int lane = t & 31, wid = t >> 5;
    for (int r = 0; r < NS; r++) {
        unsigned long long best = 0ull;
        for (int p = t; p < NPIX; p += 1024) {
            unsigned long long cand =
                ((unsigned long long)sc[p] << 32) | (unsigned long long)(0xFFFFFFFFu - (uint32_t)p);
            if (cand > best) best = cand;
        }
        #pragma unroll
        for (int o = 16; o > 0; o >>= 1) {
            unsigned long long other = __shfl_down_sync(0xFFFFFFFFu, best, o);
            if (other > best) best = other;
        }
        if (lane == 0) warpbest[wid] = best;
        __syncthreads();
        if (wid == 0) {
            best = warpbest[lane];
            #pragma unroll
            for (int o = 16; o > 0; o >>= 1) {
                unsigned long long other = __shfl_down_sync(0xFFFFFFFFu, best, o);
                if (other > best) best = other;
            }
            if (lane == 0) {
                int idx = (int)(0xFFFFFFFFu - (uint32_t)(best & 0xFFFFFFFFull));
                g_sel_idx[(b * 2 + cls) * NS + r] = idx;
                sc[idx] = 0u;   // remove from further rounds
            }
        }
        __syncthreads();
    }
}

// ---------------- kernel 3: train features, mean/std, standardize ----------------
__global__ void k_train(const float* __restrict__ img) {
    __shared__ float feats[100 * 5];
    __shared__ float ms[10];
    int b = blockIdx.x, t = threadIdx.x;
    const float* base = img + (size_t)b * NPIX * 3;

    if (t < 100) {
        int p = (t < 50) ? g_sel_idx[(b * 2 + 0) * NS + t]
                         : g_sel_idx[(b * 2 + 1) * NS + (t - 50)];
        int i = p / WW, j = p % WW;
        feats[t * 5 + 0] = clip255(base[p * 3 + 0]) / 255.0f;
        feats[t * 5 + 1] = clip255(base[p * 3 + 1]) / 255.0f;
        feats[t * 5 + 2] = clip255(base[p * 3 + 2]) / 255.0f;
        feats[t * 5 + 3] = ((float)i / 96.0f) * 100.0f;
        feats[t * 5 + 4] = ((float)j / 96.0f) * 100.0f;
    }
    __syncthreads();
    if (t < 5) {
        float s = 0.0f;
        for (int r = 0; r < 100; r++) s += feats[r * 5 + t];
        float m = s / 100.0f;
        float v = 0.0f;
        for (int r = 0; r < 100; r++) { float d = feats[r * 5 + t] - m; v += d * d; }
        ms[t] = m;
        ms[5 + t] = sqrtf(v / 100.0f);
    }
    __syncthreads();
    if (t < 100) {
        #pragma unroll
        for (int f = 0; f < 5; f++)
            g_train[(b * 100 + t) * 5 + f] = (feats[t * 5 + f] - ms[f]) / ms[5 + f];
    }
    if (t < 10) g_meanstd[b * 10 + t] = ms[t];
}

// ---------------- kernel 4: KNN segmentation + masking ----------------
__global__ void k_seg(const float* __restrict__ img, float* __restrict__ out) {
    __shared__ float tr[500];
    __shared__ float ms[10];
    int b = blockIdx.y, t = threadIdx.x;
    for (int k = t; k < 500; k += 256) tr[k] = g_train[b * 500 + k];
    if (t < 10) ms[t] = g_meanstd[b * 10 + t];
    __syncthreads();

    int p = blockIdx.x * 256 + t;
    const float* px = img + ((size_t)b * NPIX + p) * 3;
    float c0 = clip255(px[0]), c1 = clip255(px[1]), c2 = clip255(px[2]);
    int i = p / WW, j = p % WW;

    float ts[5];
    ts[0] = (c0 / 255.0f - ms[0]) / ms[5];
    ts[1] = (c1 / 255.0f - ms[1]) / ms[6];
    ts[2] = (c2 / 255.0f - ms[2]) / ms[7];
    ts[3] = (((float)i / 96.0f) * 100.0f - ms[3]) / ms[8];
    ts[4] = (((float)j / 96.0f) * 100.0f - ms[4]) / ms[9];

    // top-5 smallest sqrt-distances; strict '<' keeps first occurrence
    // (matches lax.top_k lowest-index tiebreak on equal dist).
    float bd[KNN] = {3.4e38f, 3.4e38f, 3.4e38f, 3.4e38f, 3.4e38f};
    int   bl[KNN] = {0, 0, 0, 0, 0};
    for (int n = 0; n < 100; n++) {
        float d2 = 0.0f;
        #pragma unroll
        for (int f = 0; f < 5; f++) { float df = ts[f] - tr[n * 5 + f]; d2 += df * df; }
        float ds = sqrtf(d2);   // compare on sqrt like the reference (ties matter)
        if (ds < bd[KNN - 1]) {
            int pos = KNN - 1;
            while (pos > 0 && ds < bd[pos - 1]) {
                bd[pos] = bd[pos - 1]; bl[pos] = bl[pos - 1]; pos--;
            }
            bd[pos] = ds; bl[pos] = (n < 50) ? 1 : 0;
        }
    }
    int cnt = bl[0] + bl[1] + bl[2] + bl[3] + bl[4];
    float* o = out + ((size_t)b * NPIX + p) * 3;
    if (cnt >= 2) { o[0] = c0; o[1] = c1; o[2] = c2; }
    else          { o[0] = 0.0f; o[1] = 0.0f; o[2] = 0.0f; }
}

// ---------------- launch ----------------
extern "C" void kernel_launch(void* const* d_in, const int* in_sizes, int n_in,
                              void* d_out, int out_size) {
    const float* img = (const float*)d_in[0];
    float* out = (float*)d_out;
    k_cmax<<<NB, 256>>>(img);
    k_select<<<NB * 2, 1024>>>(img);
    k_train<<<NB, 128>>>(img);
    k_seg<<<dim3(NPIX / 256, NB), 256>>>(img, out);
}

// round 4
// speedup vs baseline: 2.6026x; 2.6026x over previous
#include <cuda_runtime.h>
#include <stdint.h>
#include <math.h>

#define HH 96
#define WW 96
#define NPIX 9216
#define NB 32
#define NS 50

// ---------------- scratch ----------------
__device__ int g_sel_idx[NB * 2 * NS];   // [img][cls][50] in rank order

// ---------------- threefry2x32 ----------------
__device__ __forceinline__ void tf2x32(uint32_t k0, uint32_t k1,
                                       uint32_t c0, uint32_t c1,
                                       uint32_t& o0, uint32_t& o1) {
    uint32_t ks2 = k0 ^ k1 ^ 0x1BD11BDAu;
    uint32_t x0 = c0 + k0, x1 = c1 + k1;
#define TF_RND(r) { x0 += x1; x1 = (x1 << (r)) | (x1 >> (32 - (r))); x1 ^= x0; }
    TF_RND(13) TF_RND(15) TF_RND(26) TF_RND(6)   x0 += k1;  x1 += ks2 + 1u;
    TF_RND(17) TF_RND(29) TF_RND(16) TF_RND(24)  x0 += ks2; x1 += k0 + 2u;
    TF_RND(13) TF_RND(15) TF_RND(26) TF_RND(6)   x0 += k0;  x1 += k1 + 3u;
    TF_RND(17) TF_RND(29) TF_RND(16) TF_RND(24)  x0 += k1;  x1 += ks2 + 4u;
    TF_RND(13) TF_RND(15) TF_RND(26) TF_RND(6)   x0 += ks2; x1 += k0 + 5u;
#undef TF_RND
    o0 = x0; o1 = x1;
}

// partitionable threefry key derivation (matches passing R2 kernel)
__device__ __forceinline__ void image_keys(int b, uint32_t& f0, uint32_t& f1,
                                           uint32_t& g0, uint32_t& g1) {
    uint32_t kb0, kb1;
    tf2x32(0u, 42u, 0u, (uint32_t)b, kb0, kb1);
    tf2x32(kb0, kb1, 0u, 0u, f0, f1);
    tf2x32(kb0, kb1, 0u, 1u, g0, g1);
}

// raw random bits for pixel p (ordering of uniform(p) == ordering of bits>>9)
__device__ __forceinline__ uint32_t rbits(uint32_t k0, uint32_t k1, int p) {
    uint32_t o0, o1;
    tf2x32(k0, k1, 0u, (uint32_t)p, o0, o1);
    return o0 ^ o1;
}

__device__ __forceinline__ float clip255(float x) {
    return fminf(fmaxf(x / 255.0f, 0.0f), 1.0f);
}

// ============ kernel 1: cmax + top-50 selection (fg & bg) ============
// blockIdx.x = image*2 + cls. Preserves exact lax.top_k order in g_sel_idx.
__global__ void __launch_bounds__(1024) k_select(const float* __restrict__ img) {
    __shared__ uint32_t rv[NPIX];          // (bits>>9)+1 if valid else 0
    __shared__ uint32_t hist[257];
    __shared__ float cm[3];
    __shared__ float wred[32 * 3];
    __shared__ unsigned long long cand[512];
    __shared__ uint32_t skey[2];
    __shared__ int s_cnt, s_pivot;

    int blk = blockIdx.x, b = blk >> 1, cls = blk & 1;
    int t = threadIdx.x, lane = t & 31, wid = t >> 5;
    const float* base = img + (size_t)b * NPIX * 3;

    if (t == 0) {
        uint32_t f0, f1, g0, g1;
        image_keys(b, f0, f1, g0, g1);
        skey[0] = cls ? g0 : f0;
        skey[1] = cls ? g1 : f1;
    }
    if (t < 257) hist[t] = 0u;

    // --- per-channel max of img_p ---
    float m0 = -3.4e38f, m1 = -3.4e38f, m2 = -3.4e38f;
    for (int p = t; p < NPIX; p += 1024) {
        m0 = fmaxf(m0, clip255(base[p * 3 + 0]));
        m1 = fmaxf(m1, clip255(base[p * 3 + 1]));
        m2 = fmaxf(m2, clip255(base[p * 3 + 2]));
    }
    #pragma unroll
    for (int o = 16; o > 0; o >>= 1) {
        m0 = fmaxf(m0, __shfl_xor_sync(0xFFFFFFFFu, m0, o));
        m1 = fmaxf(m1, __shfl_xor_sync(0xFFFFFFFFu, m1, o));
        m2 = fmaxf(m2, __shfl_xor_sync(0xFFFFFFFFu, m2, o));
    }
    if (lane == 0) { wred[wid * 3 + 0] = m0; wred[wid * 3 + 1] = m1; wred[wid * 3 + 2] = m2; }
    __syncthreads();
    if (t < 3) {
        float m = -3.4e38f;
        for (int w = 0; w < 32; w++) m = fmaxf(m, wred[w * 3 + t]);
        cm[t] = m;
    }
    __syncthreads();

    // --- rv + histogram ---
    uint32_t k0 = skey[0], k1 = skey[1];
    float c0m = cm[0], c1m = cm[1], c2m = cm[2];
    for (int p = t; p < NPIX; p += 1024) {
        float v0 = clip255(base[p * 3 + 0]) / c0m;
        float v1 = clip255(base[p * 3 + 1]) / c1m;
        float v2 = clip255(base[p * 3 + 2]) / c2m;
        bool fg = (v0 > 0.0f && v0 < 0.6f) || (v1 > 0.0f && v1 < 0.6f) || (v2 > 0.0f && v2 < 0.6f);
        bool valid = cls ? !fg : fg;
        uint32_t r = 0;
        if (valid) {
            uint32_t bits = rbits(k0, k1, p);
            r = (bits >> 9) + 1u;
            atomicAdd(&hist[(bits >> 24) + 1u], 1u);
        }
        rv[p] = r;
    }
    __syncthreads();

    if (t == 0) {
        int cum = 0, pivot = 0;
        for (int bin = 256; bin >= 1; bin--) {
            cum += (int)hist[bin];
            if (cum >= NS) { pivot = bin; break; }
        }
        s_pivot = pivot;
        s_cnt = 0;
    }
    __syncthreads();

    int pivot = s_pivot;
    for (int p = t; p < NPIX; p += 1024) {
        uint32_t v = rv[p];
        bool take;
        if (pivot >= 1) take = (v != 0u) && ((int)(((v - 1u) >> 15) + 1u) >= pivot);
        else            take = (v != 0u) || (p < 100);   // <50 valid: lowest-index invalids are in p<100
        if (take) {
            int slot = atomicAdd(&s_cnt, 1);
            if (slot < 512)
                cand[slot] = ((unsigned long long)v << 23) |
                             ((unsigned long long)(NPIX - 1 - p) << 9) |
                             (unsigned long long)slot;
        }
    }
    __syncthreads();

    // --- warp 0: 50 argmax rounds over <=~150 candidates (rank order) ---
    if (t < 32) {
        int cnt = s_cnt < 512 ? s_cnt : 512;
        for (int r = 0; r < NS; r++) {
            unsigned long long best = 0ull;
            for (int i = t; i < cnt; i += 32) {
                unsigned long long c = cand[i];
                if (c > best) best = c;
            }
            #pragma unroll
            for (int o = 16; o > 0; o >>= 1) {
                unsigned long long ob = __shfl_xor_sync(0xFFFFFFFFu, best, o);
                if (ob > best) best = ob;
            }
            if (t == 0) {
                cand[best & 511ull] = 0ull;
                int p = NPIX - 1 - (int)((best >> 9) & 0x3FFFull);
                g_sel_idx[blk * NS + r] = p;
            }
            __syncwarp();
        }
    }
}

// ============ kernel 2: train stats + KNN segmentation + masking ============
__global__ void __launch_bounds__(256) k_seg(const float* __restrict__ img,
                                             float* __restrict__ out) {
    __shared__ float4 tr4[200];   // 100 rows x 8 floats (5 used)
    __shared__ float ms[10];
    float* tr = (float*)tr4;
    int b = blockIdx.y, t = threadIdx.x;
    const float* base = img + (size_t)b * NPIX * 3;

    if (t < 100) {
        int p = (t < 50) ? g_sel_idx[(b * 2 + 0) * NS + t]
                         : g_sel_idx[(b * 2 + 1) * NS + (t - 50)];
        int i = p / WW, j = p % WW;
        tr[t * 8 + 0] = clip255(base[p * 3 + 0]) / 255.0f;
        tr[t * 8 + 1] = clip255(base[p * 3 + 1]) / 255.0f;
        tr[t * 8 + 2] = clip255(base[p * 3 + 2]) / 255.0f;
        tr[t * 8 + 3] = ((float)i / 96.0f) * 100.0f;
        tr[t * 8 + 4] = ((float)j / 96.0f) * 100.0f;
        tr[t * 8 + 5] = 0.0f; tr[t * 8 + 6] = 0.0f; tr[t * 8 + 7] = 0.0f;
    }
    __syncthreads();
    if (t < 5) {
        float s = 0.0f;
        for (int r = 0; r < 100; r++) s += tr[r * 8 + t];
        float m = s / 100.0f;
        float v = 0.0f;
        for (int r = 0; r < 100; r++) { float d = tr[r * 8 + t] - m; v += d * d; }
        ms[t] = m;
        ms[5 + t] = sqrtf(v / 100.0f);
    }
    __syncthreads();
    if (t < 100) {
        #pragma unroll
        for (int f = 0; f < 5; f++)
            tr[t * 8 + f] = (tr[t * 8 + f] - ms[f]) / ms[5 + f];
    }
    __syncthreads();

    int p = blockIdx.x * 256 + t;
    float c0 = clip255(base[p * 3 + 0]);
    float c1 = clip255(base[p * 3 + 1]);
    float c2 = clip255(base[p * 3 + 2]);
    int i = p / WW, j = p % WW;

    float ts0 = (c0 / 255.0f - ms[0]) / ms[5];
    float ts1 = (c1 / 255.0f - ms[1]) / ms[6];
    float ts2 = (c2 / 255.0f - ms[2]) / ms[7];
    float ts3 = (((float)i / 96.0f) * 100.0f - ms[3]) / ms[8];
    float ts4 = (((float)j / 96.0f) * 100.0f - ms[9 - 5]) / ms[9];   // ms[4], ms[9]

    const float INF = __int_as_float(0x7F800000);
    // fg: 2 smallest d2; bg: 4 smallest d2 (value-level; order stats commute with sqrt)
    float a1 = INF, a2 = INF;
    float b1 = INF, b2 = INF, b3 = INF, b4 = INF;

    #pragma unroll 5
    for (int n = 0; n < 50; n++) {
        float4 A = tr4[2 * n], B = tr4[2 * n + 1];
        float df0 = ts0 - A.x; float d2 = df0 * df0;
        float df1 = ts1 - A.y; d2 += df1 * df1;
        float df2 = ts2 - A.z; d2 += df2 * df2;
        float df3 = ts3 - A.w; d2 += df3 * df3;
        float df4 = ts4 - B.x; d2 += df4 * df4;
        float u = fmaxf(d2, a1);
        a2 = fminf(u, a2);
        a1 = fminf(d2, a1);
    }
    #pragma unroll 5
    for (int n = 50; n < 100; n++) {
        float4 A = tr4[2 * n], B = tr4[2 * n + 1];
        float df0 = ts0 - A.x; float d2 = df0 * df0;
        float df1 = ts1 - A.y; d2 += df1 * df1;
        float df2 = ts2 - A.z; d2 += df2 * df2;
        float df3 = ts3 - A.w; d2 += df3 * df3;
        float df4 = ts4 - B.x; d2 += df4 * df4;
        float u3 = fmaxf(d2, b3), u2 = fmaxf(d2, b2), u1 = fmaxf(d2, b1);
        b4 = fminf(u3, b4);
        b3 = fminf(u2, b3);
        b2 = fminf(u1, b2);
        b1 = fminf(d2, b1);
    }

    // seg=1 iff >=2 fg among top-5 by (sqrt(d2), index) lex order:
    // 2nd-min fg sqrt-dist <= 4th-min bg sqrt-dist (fg indices precede bg -> ties favor fg)
    bool seg = (sqrtf(a2) <= sqrtf(b4));
    float* o = out + ((size_t)b * NPIX + p) * 3;
    if (seg) { o[0] = c0; o[1] = c1; o[2] = c2; }
    else     { o[0] = 0.0f; o[1] = 0.0f; o[2] = 0.0f; }
}

// ---------------- launch ----------------
extern "C" void kernel_launch(void* const* d_in, const int* in_sizes, int n_in,
                              void* d_out, int out_size) {
    const float* img = (const float*)d_in[0];
    float* out = (float*)d_out;
    k_select<<<NB * 2, 1024>>>(img);
    k_seg<<<dim3(NPIX / 256, NB), 256>>>(img, out);
}

// round 6
// speedup vs baseline: 3.6455x; 1.4007x over previous
#include <cuda_runtime.h>
#include <stdint.h>
#include <math.h>

#define HH 96
#define WW 96
#define NPIX 9216
#define NB 32
#define NS 50

// ---------------- scratch ----------------
__device__ int   g_sel_idx[NB * 2 * NS];      // [img][cls][50] rank order
__device__ float g_trp[NB * 50 * 6 * 2];      // negated standardized, pair-packed
__device__ float g_ms[NB * 10];               // mean[5], std[5]

// ---------------- threefry2x32 ----------------
__device__ __forceinline__ void tf2x32(uint32_t k0, uint32_t k1,
                                       uint32_t c0, uint32_t c1,
                                       uint32_t& o0, uint32_t& o1) {
    uint32_t ks2 = k0 ^ k1 ^ 0x1BD11BDAu;
    uint32_t x0 = c0 + k0, x1 = c1 + k1;
#define TF_RND(r) { x0 += x1; x1 = (x1 << (r)) | (x1 >> (32 - (r))); x1 ^= x0; }
    TF_RND(13) TF_RND(15) TF_RND(26) TF_RND(6)   x0 += k1;  x1 += ks2 + 1u;
    TF_RND(17) TF_RND(29) TF_RND(16) TF_RND(24)  x0 += ks2; x1 += k0 + 2u;
    TF_RND(13) TF_RND(15) TF_RND(26) TF_RND(6)   x0 += k0;  x1 += k1 + 3u;
    TF_RND(17) TF_RND(29) TF_RND(16) TF_RND(24)  x0 += k1;  x1 += ks2 + 4u;
    TF_RND(13) TF_RND(15) TF_RND(26) TF_RND(6)   x0 += ks2; x1 += k0 + 5u;
#undef TF_RND
    o0 = x0; o1 = x1;
}

__device__ __forceinline__ void image_keys(int b, uint32_t& f0, uint32_t& f1,
                                           uint32_t& g0, uint32_t& g1) {
    uint32_t kb0, kb1;
    tf2x32(0u, 42u, 0u, (uint32_t)b, kb0, kb1);
    tf2x32(kb0, kb1, 0u, 0u, f0, f1);
    tf2x32(kb0, kb1, 0u, 1u, g0, g1);
}

__device__ __forceinline__ uint32_t rbits(uint32_t k0, uint32_t k1, int p) {
    uint32_t o0, o1;
    tf2x32(k0, k1, 0u, (uint32_t)p, o0, o1);
    return o0 ^ o1;
}

__device__ __forceinline__ float clip255(float x) {
    return fminf(fmaxf(x / 255.0f, 0.0f), 1.0f);
}

// ---------------- packed f32x2 helpers ----------------
__device__ __forceinline__ uint64_t pk2(float lo, float hi) {
    uint64_t r; asm("mov.b64 %0, {%1, %2};" : "=l"(r) : "f"(lo), "f"(hi)); return r;
}
__device__ __forceinline__ void unpk2(float& lo, float& hi, uint64_t v) {
    asm("mov.b64 {%0, %1}, %2;" : "=f"(lo), "=f"(hi) : "l"(v));
}
__device__ __forceinline__ uint64_t add2(uint64_t a, uint64_t b) {
    uint64_t r; asm("add.rn.f32x2 %0, %1, %2;" : "=l"(r) : "l"(a), "l"(b)); return r;
}
__device__ __forceinline__ uint64_t mul2(uint64_t a, uint64_t b) {
    uint64_t r; asm("mul.rn.f32x2 %0, %1, %2;" : "=l"(r) : "l"(a), "l"(b)); return r;
}
__device__ __forceinline__ uint64_t fma2(uint64_t a, uint64_t b, uint64_t c) {
    uint64_t r; asm("fma.rn.f32x2 %0, %1, %2, %3;" : "=l"(r) : "l"(a), "l"(b), "l"(c)); return r;
}

// ============ kernel 1: cmax + top-50 selection ============
__global__ void __launch_bounds__(1024) k_select(const float* __restrict__ img) {
    __shared__ uint32_t hist[256];
    __shared__ unsigned long long cand[512];
    __shared__ uint32_t cmu[3];
    __shared__ uint32_t skey[2];
    __shared__ int s_cnt, s_pivot;

    int blk = blockIdx.x, b = blk >> 1, cls = blk & 1;
    int t = threadIdx.x;
    const float* base = img + (size_t)b * NPIX * 3;

    if (t == 0) {
        uint32_t f0, f1, g0, g1;
        image_keys(b, f0, f1, g0, g1);
        skey[0] = cls ? g0 : f0;
        skey[1] = cls ? g1 : f1;
        s_cnt = 0;
    }
    if (t < 256) hist[t] = 0u;
    if (t < 3) cmu[t] = 0u;
    __syncthreads();

    uint32_t k0 = skey[0], k1 = skey[1];

    // pass 1: cmax + random bits (overlaps threefry ALU with image loads)
    uint32_t bt[9];
    float m0 = 0.0f, m1 = 0.0f, m2 = 0.0f;
    #pragma unroll
    for (int q = 0; q < 9; q++) {
        int p = t + q * 1024;
        m0 = fmaxf(m0, clip255(base[p * 3 + 0]));
        m1 = fmaxf(m1, clip255(base[p * 3 + 1]));
        m2 = fmaxf(m2, clip255(base[p * 3 + 2]));
        bt[q] = rbits(k0, k1, p);
    }
    uint32_t r0 = __reduce_max_sync(0xFFFFFFFFu, __float_as_uint(m0));
    uint32_t r1 = __reduce_max_sync(0xFFFFFFFFu, __float_as_uint(m1));
    uint32_t r2 = __reduce_max_sync(0xFFFFFFFFu, __float_as_uint(m2));
    if ((t & 31) == 0) {
        atomicMax(&cmu[0], r0); atomicMax(&cmu[1], r1); atomicMax(&cmu[2], r2);
    }
    __syncthreads();

    float c0m = __uint_as_float(cmu[0]);
    float c1m = __uint_as_float(cmu[1]);
    float c2m = __uint_as_float(cmu[2]);

    // pass 2: validity + histogram of bits>>24 over valid pixels
    int vmask = 0;
    #pragma unroll
    for (int q = 0; q < 9; q++) {
        int p = t + q * 1024;
        float v0 = clip255(base[p * 3 + 0]) / c0m;
        float v1 = clip255(base[p * 3 + 1]) / c1m;
        float v2 = clip255(base[p * 3 + 2]) / c2m;
        bool fg = (v0 > 0.0f && v0 < 0.6f) || (v1 > 0.0f && v1 < 0.6f) || (v2 > 0.0f && v2 < 0.6f);
        bool valid = cls ? !fg : fg;
        if (valid) {
            vmask |= (1 << q);
            atomicAdd(&hist[bt[q] >> 24], 1u);
        }
    }
    __syncthreads();

    // pivot: warp-parallel suffix scan over 256 bins
    if (t < 32) {
        int csum = 0;
        #pragma unroll
        for (int i = 0; i < 8; i++) csum += (int)hist[t * 8 + i];
        int suf = csum;
        #pragma unroll
        for (int o = 1; o < 32; o <<= 1) {
            int v = __shfl_down_sync(0xFFFFFFFFu, suf, o);
            if (t + o < 32) suf += v;
        }
        unsigned ball = __ballot_sync(0xFFFFFFFFu, suf >= NS);
        if (ball) {
            int L = 31 - __clz(ball);
            if (t == L) {
                int acc = suf - csum;   // suffix of chunks above L
                int pv = 8 * L;
                for (int bin = 8 * L + 7; bin >= 8 * L; bin--) {
                    acc += (int)hist[bin];
                    if (acc >= NS) { pv = bin; break; }
                }
                s_pivot = pv;
            }
        } else if (t == 0) s_pivot = -1;
    }
    __syncthreads();

    // collect candidates
    int pivot = s_pivot;
    #pragma unroll
    for (int q = 0; q < 9; q++) {
        int p = t + q * 1024;
        bool valid = (vmask >> q) & 1;
        uint32_t v = valid ? (bt[q] >> 9) + 1u : 0u;
        bool take;
        if (pivot >= 0) take = valid && ((int)(bt[q] >> 24) >= pivot);
        else            take = valid || (p < 100);  // few-valid fallback
        if (take) {
            int slot = atomicAdd(&s_cnt, 1);
            if (slot < 512)
                cand[slot] = ((unsigned long long)v << 14) |
                             (unsigned long long)(NPIX - 1 - p);
        }
    }
    __syncthreads();

    // rank by all-pairs count (keys unique) -> exact lax.top_k order
    int cnt = s_cnt < 512 ? s_cnt : 512;
    if (t < cnt) {
        unsigned long long ki = cand[t];
        int rank = 0;
        for (int j = 0; j < cnt; j++) rank += (cand[j] > ki);
        if (rank < NS) {
            int p = NPIX - 1 - (int)(ki & 0x3FFFull);
            g_sel_idx[blk * NS + rank] = p;
        }
    }
}

// ============ kernel 2: train stats + packed negated train matrix ============
__global__ void __launch_bounds__(128) k_train(const float* __restrict__ img) {
    __shared__ float fe[100 * 5];
    __shared__ float ms[10];
    int b = blockIdx.x, t = threadIdx.x;
    const float* base = img + (size_t)b * NPIX * 3;

    if (t < 100) {
        int p = (t < 50) ? g_sel_idx[(b * 2 + 0) * NS + t]
                         : g_sel_idx[(b * 2 + 1) * NS + (t - 50)];
        int i = p / WW, j = p % WW;
        fe[t * 5 + 0] = clip255(base[p * 3 + 0]) / 255.0f;
        fe[t * 5 + 1] = clip255(base[p * 3 + 1]) / 255.0f;
        fe[t * 5 + 2] = clip255(base[p * 3 + 2]) / 255.0f;
        fe[t * 5 + 3] = ((float)i / 96.0f) * 100.0f;
        fe[t * 5 + 4] = ((float)j / 96.0f) * 100.0f;
    }
    __syncthreads();
    if (t < 5) {
        float s = 0.0f;
        for (int r = 0; r < 100; r++) s += fe[r * 5 + t];
        float m = s / 100.0f;
        float v = 0.0f;
        for (int r = 0; r < 100; r++) { float d = fe[r * 5 + t] - m; v += d * d; }
        ms[t] = m;
        ms[5 + t] = sqrtf(v / 100.0f);
    }
    __syncthreads();
    if (t < 100) {
        int m = t >> 1, h = t & 1;
        float* dst = g_trp + ((size_t)b * 50 + m) * 12;
        #pragma unroll
        for (int f = 0; f < 5; f++)
            dst[f * 2 + h] = -((fe[t * 5 + f] - ms[f]) / ms[5 + f]);
        dst[5 * 2 + h] = 0.0f;
    }
    if (t < 10) g_ms[b * 10 + t] = ms[t];
}

// ============ kernel 3: KNN segmentation + masking (packed f32x2) ============
__global__ void __launch_bounds__(256) k_seg(const float* __restrict__ img,
                                             float* __restrict__ out) {
    __shared__ ulonglong2 stq[150];  // 50 pairs x 3 ulonglong2 = 600 floats (2400B)
    __shared__ float ms[10];
    int b = blockIdx.y, t = threadIdx.x;
    const float* base = img + (size_t)b * NPIX * 3;

    if (t < 150) ((float4*)stq)[t] = ((const float4*)(g_trp + (size_t)b * 600))[t];
    if (t < 10) ms[t] = g_ms[b * 10 + t];
    __syncthreads();

    int p = blockIdx.x * 256 + t;
    float c0 = clip255(base[p * 3 + 0]);
    float c1 = clip255(base[p * 3 + 1]);
    float c2 = clip255(base[p * 3 + 2]);
    int i = p / WW, j = p % WW;

    float ts0 = (c0 / 255.0f - ms[0]) / ms[5];
    float ts1 = (c1 / 255.0f - ms[1]) / ms[6];
    float ts2 = (c2 / 255.0f - ms[2]) / ms[7];
    float ts3 = (((float)i / 96.0f) * 100.0f - ms[3]) / ms[8];
    float ts4 = (((float)j / 96.0f) * 100.0f - ms[4]) / ms[9];

    uint64_t tp0 = pk2(ts0, ts0), tp1 = pk2(ts1, ts1), tp2 = pk2(ts2, ts2);
    uint64_t tp3 = pk2(ts3, ts3), tp4 = pk2(ts4, ts4);

    const float INF = __int_as_float(0x7F800000);
    float a1 = INF, a2 = INF;                       // 2 smallest fg d2
    float b1 = INF, b2 = INF, b3 = INF, b4 = INF;   // 4 smallest bg d2

    #pragma unroll 5
    for (int m = 0; m < 25; m++) {                  // fg pairs
        ulonglong2 q0 = stq[3 * m], q1 = stq[3 * m + 1], q2 = stq[3 * m + 2];
        uint64_t d0 = add2(tp0, q0.x), d1 = add2(tp1, q0.y);
        uint64_t d2_ = add2(tp2, q1.x), d3 = add2(tp3, q1.y);
        uint64_t d4 = add2(tp4, q2.x);
        uint64_t s = mul2(d0, d0);
        s = fma2(d1, d1, s); s = fma2(d2_, d2_, s);
        s = fma2(d3, d3, s); s = fma2(d4, d4, s);
        float lo, hi; unpk2(lo, hi, s);
        float u = fmaxf(lo, a1); a2 = fminf(u, a2); a1 = fminf(lo, a1);
        u = fmaxf(hi, a1);       a2 = fminf(u, a2); a1 = fminf(hi, a1);
    }
    #pragma unroll 5
    for (int m = 25; m < 50; m++) {                 // bg pairs
        ulonglong2 q0 = stq[3 * m], q1 = stq[3 * m + 1], q2 = stq[3 * m + 2];
        uint64_t d0 = add2(tp0, q0.x), d1 = add2(tp1, q0.y);
        uint64_t d2_ = add2(tp2, q1.x), d3 = add2(tp3, q1.y);
        uint64_t d4 = add2(tp4, q2.x);
        uint64_t s = mul2(d0, d0);
        s = fma2(d1, d1, s); s = fma2(d2_, d2_, s);
        s = fma2(d3, d3, s); s = fma2(d4, d4, s);
        float lo, hi; unpk2(lo, hi, s);
        float u3 = fmaxf(lo, b3), u2 = fmaxf(lo, b2), u1 = fmaxf(lo, b1);
        b4 = fminf(u3, b4); b3 = fminf(u2, b3); b2 = fminf(u1, b2); b1 = fminf(lo, b1);
        u3 = fmaxf(hi, b3); u2 = fmaxf(hi, b2); u1 = fmaxf(hi, b1);
        b4 = fminf(u3, b4); b3 = fminf(u2, b3); b2 = fminf(u1, b2); b1 = fminf(hi, b1);
    }

    // seg = 1 iff 2nd-min fg sqrt-dist <= 4th-min bg sqrt-dist (sqrt-domain,
    // '<=' reproduces lax.top_k lowest-index tiebreak: fg indices precede bg)
    bool seg = (sqrtf(a2) <= sqrtf(b4));
    float* o = out + ((size_t)b * NPIX + p) * 3;
    if (seg) { o[0] = c0; o[1] = c1; o[2] = c2; }
    else     { o[0] = 0.0f; o[1] = 0.0f; o[2] = 0.0f; }
}

// ---------------- launch ----------------
extern "C" void kernel_launch(void* const* d_in, const int* in_sizes, int n_in,
                              void* d_out, int out_size) {
    const float* img = (const float*)d_in[0];
    float* out = (float*)d_out;
    k_select<<<NB * 2, 1024>>>(img);
    k_train<<<NB, 128>>>(img);
    k_seg<<<dim3(NPIX / 256, NB), 256>>>(img, out);
}